// round 1
// baseline (speedup 1.0000x reference)
#include <cuda_runtime.h>

// Problem constants
#define CB 4
#define CS 4096
#define CD 256
#define CT 256
#define CK 16
#define CIN 259  // 3 + D

typedef long long ll;

// -------- device scratch (allocation-free: static globals) --------
__device__ float g_feat[CB * CS * CD];                 // 16 MB packed features
__device__ float g_sq[CB * CS];
__device__ float g_gram[(size_t)CB * CS * CS];         // 256 MB Gram
__device__ int   g_idx[CB * CS * CK];
__device__ float g_h[CB * CS * CT];
__device__ float g_q[CB * CS * CT];
__device__ float g_k[CB * CS * CT];
__device__ float g_v[CB * CS * CT];
__device__ float g_rel[(size_t)CB * CS * CK * CT];     // 256 MB
__device__ float g_t1[(size_t)CB * CS * CK * CT];      // 256 MB
__device__ float g_attn[(size_t)CB * CS * CK * CT];    // 256 MB
__device__ float g_res[CB * CS * CT];

// -------- pack: split x into pos (-> d_out) and packed feat --------
__global__ void pack_kernel(const float* __restrict__ x, float* __restrict__ pos) {
    int i = blockIdx.x * blockDim.x + threadIdx.x;
    const int total = CB * CS * CIN;
    for (; i < total; i += gridDim.x * blockDim.x) {
        int bs = i / CIN;
        int c  = i % CIN;
        float v = x[i];
        if (c < 3) pos[bs * 3 + c] = v;
        else       g_feat[bs * CD + (c - 3)] = v;
    }
}

// -------- sq[p] = sum_d feat[p][d]^2 (one warp per point) --------
__global__ void sq_kernel() {
    int p = blockIdx.x * 8 + (threadIdx.x >> 5);
    int lane = threadIdx.x & 31;
    const float* f = g_feat + (ll)p * CD;
    float s = 0.f;
    #pragma unroll
    for (int d = lane; d < CD; d += 32) { float v = f[d]; s += v * v; }
    #pragma unroll
    for (int o = 16; o; o >>= 1) s += __shfl_xor_sync(0xFFFFFFFFu, s, o);
    if (!lane) g_sq[p] = s;
}

// -------- generic tiled SGEMM: C = A(MxK) * B(KxN) [+bias][relu][+res] --------
// TRANS_B: B stored row-major NxK (used for Gram A*A^T)
template <bool TRANS_B, bool RELU, bool ADD_RES, bool BIAS>
__global__ __launch_bounds__(256)
void sgemm_kernel(const float* __restrict__ A, const float* __restrict__ Bm,
                  const float* __restrict__ bias, const float* __restrict__ Rres,
                  float* __restrict__ C,
                  int M, int N, int Kd, ll sA, ll sB, ll sC) {
    const int tid = threadIdx.x;
    const int tx = tid & 15, ty = tid >> 4;
    const ll z = blockIdx.z;
    A  += z * sA;
    Bm += z * sB;
    C  += z * sC;
    const int bm = blockIdx.y * 64;
    const int bn = blockIdx.x * 64;

    __shared__ float As[16][68];
    __shared__ float Bs[16][68];

    float acc[4][4] = {};

    const int lr = tid >> 2;          // 0..63
    const int lc = (tid & 3) << 2;    // 0,4,8,12
    const int bc = tid >> 4;          // 0..15
    const int bj = (tid & 15) << 2;   // 0..60

    const float* Aptr = A + (ll)(bm + lr) * Kd + lc;

    for (int k0 = 0; k0 < Kd; k0 += 16) {
        float4 a = *(const float4*)(Aptr + k0);
        As[lc + 0][lr] = a.x; As[lc + 1][lr] = a.y;
        As[lc + 2][lr] = a.z; As[lc + 3][lr] = a.w;
        if (TRANS_B) {
            float4 bv = *(const float4*)(Bm + (ll)(bn + lr) * Kd + k0 + lc);
            Bs[lc + 0][lr] = bv.x; Bs[lc + 1][lr] = bv.y;
            Bs[lc + 2][lr] = bv.z; Bs[lc + 3][lr] = bv.w;
        } else {
            float4 bv = *(const float4*)(Bm + (ll)(k0 + bc) * N + bn + bj);
            *(float4*)&Bs[bc][bj] = bv;
        }
        __syncthreads();
        #pragma unroll
        for (int kk = 0; kk < 16; kk++) {
            float4 a4 = *(const float4*)&As[kk][ty << 2];
            float4 b4 = *(const float4*)&Bs[kk][tx << 2];
            acc[0][0] += a4.x * b4.x; acc[0][1] += a4.x * b4.y;
            acc[0][2] += a4.x * b4.z; acc[0][3] += a4.x * b4.w;
            acc[1][0] += a4.y * b4.x; acc[1][1] += a4.y * b4.y;
            acc[1][2] += a4.y * b4.z; acc[1][3] += a4.y * b4.w;
            acc[2][0] += a4.z * b4.x; acc[2][1] += a4.z * b4.y;
            acc[2][2] += a4.z * b4.z; acc[2][3] += a4.z * b4.w;
            acc[3][0] += a4.w * b4.x; acc[3][1] += a4.w * b4.y;
            acc[3][2] += a4.w * b4.z; acc[3][3] += a4.w * b4.w;
        }
        __syncthreads();
    }

    #pragma unroll
    for (int i = 0; i < 4; i++) {
        int row = bm + (ty << 2) + i;
        #pragma unroll
        for (int j = 0; j < 4; j++) {
            int col = bn + (tx << 2) + j;
            float v = acc[i][j];
            if (BIAS)    v += bias[col];
            if (RELU)    v = v > 0.f ? v : 0.f;
            if (ADD_RES) v += Rres[(ll)row * N + col];
            C[(ll)row * N + col] = v;
        }
    }
}

// -------- top-K selection per query row (stable argsort tie-break) --------
__global__ __launch_bounds__(256)
void topk_kernel() {
    const int row = blockIdx.x;           // b*CS + n
    const int b = row >> 12;
    const int n = row & (CS - 1);
    const float* __restrict__ G  = g_gram + ((size_t)b * CS + n) * CS;
    const float* __restrict__ sq = g_sq + b * CS;
    const int t = threadIdx.x;

    // build per-thread keys: (orderable(score) << 32) | m  — unique m per thread
    unsigned long long keys[CK];
    #pragma unroll
    for (int j = 0; j < CK; j++) {
        int m = t + j * 256;
        float sc = sq[m] - 2.0f * G[m];
        unsigned u = __float_as_uint(sc);
        u = (u & 0x80000000u) ? ~u : (u | 0x80000000u);
        keys[j] = ((unsigned long long)u << 32) | (unsigned)m;
    }
    // fully-unrolled bubble sort (registers only)
    #pragma unroll
    for (int i = 0; i < CK; i++) {
        #pragma unroll
        for (int j = 0; j < CK - 1; j++) {
            if (keys[j] > keys[j + 1]) {
                unsigned long long tmp = keys[j]; keys[j] = keys[j + 1]; keys[j + 1] = tmp;
            }
        }
    }

    __shared__ unsigned long long skey[256];
    for (int k = 0; k < CK; k++) {
        unsigned long long my = keys[0];
        skey[t] = my;
        __syncthreads();
        for (int s = 128; s; s >>= 1) {
            if (t < s && skey[t + s] < skey[t]) skey[t] = skey[t + s];
            __syncthreads();
        }
        unsigned long long win = skey[0];
        __syncthreads();
        if (my == win) {  // unique winner: advance this thread's list
            #pragma unroll
            for (int j = 0; j < CK - 1; j++) keys[j] = keys[j + 1];
            keys[CK - 1] = ~0ull;
        }
        if (t == 0) g_idx[row * CK + k] = (int)(win & 0xFFFFFFFFu);
    }
}

// -------- relation[b,n,k,:] = q[b,n,:] - kf[b, idx[b,n,k], :] --------
__global__ __launch_bounds__(256)
void relation_kernel() {
    const ll rowk = blockIdx.x;           // 0 .. CB*CS*CK
    const int t = threadIdx.x;
    const ll bn = rowk / CK;
    const int b = (int)(bn >> 12);
    const int nb = g_idx[rowk];
    g_rel[rowk * CT + t] = g_q[bn * CT + t] - g_k[((ll)b * CS + nb) * CT + t];
}

// -------- softmax over K + weighted gather-sum of v --------
__global__ __launch_bounds__(256)
void softmax_res_kernel() {
    const int bn = blockIdx.x;
    const int b = bn >> 12;
    const int t = threadIdx.x;
    __shared__ int nb[CK];
    if (t < CK) nb[t] = g_idx[bn * CK + t];
    __syncthreads();

    float lg[CK];
    float mx = -1e30f;
    #pragma unroll
    for (int k = 0; k < CK; k++) {
        lg[k] = g_attn[((ll)bn * CK + k) * CT + t] * 0.0625f;  // / sqrt(256)
        mx = fmaxf(mx, lg[k]);
    }
    float se = 0.f;
    #pragma unroll
    for (int k = 0; k < CK; k++) { lg[k] = expf(lg[k] - mx); se += lg[k]; }
    const float inv = 1.f / se;
    float r = 0.f;
    #pragma unroll
    for (int k = 0; k < CK; k++)
        r += lg[k] * inv * g_v[((ll)b * CS + nb[k]) * CT + t];
    g_res[(ll)bn * CT + t] = r;
}

// -------- launch --------
extern "C" void kernel_launch(void* const* d_in, const int* in_sizes, int n_in,
                              void* d_out, int out_size) {
    const float* x     = (const float*)d_in[0];
    const float* fc1_w = (const float*)d_in[1];
    const float* fc1_b = (const float*)d_in[2];
    const float* fc2_w = (const float*)d_in[3];
    const float* fc2_b = (const float*)d_in[4];
    const float* wq_w  = (const float*)d_in[5];
    const float* wk_w  = (const float*)d_in[6];
    const float* wv_w  = (const float*)d_in[7];
    const float* g1_w  = (const float*)d_in[8];
    const float* g1_b  = (const float*)d_in[9];
    const float* g2_w  = (const float*)d_in[10];
    const float* g2_b  = (const float*)d_in[11];

    float* out     = (float*)d_out;
    float* pos     = out;                  // (B,S,3)
    float* outMain = out + CB * CS * 3;    // (B,S,D)

    float *feat, *gram, *h, *q, *k, *v, *rel, *t1, *attn, *res;
    cudaGetSymbolAddress((void**)&feat, g_feat);
    cudaGetSymbolAddress((void**)&gram, g_gram);
    cudaGetSymbolAddress((void**)&h,    g_h);
    cudaGetSymbolAddress((void**)&q,    g_q);
    cudaGetSymbolAddress((void**)&k,    g_k);
    cudaGetSymbolAddress((void**)&v,    g_v);
    cudaGetSymbolAddress((void**)&rel,  g_rel);
    cudaGetSymbolAddress((void**)&t1,   g_t1);
    cudaGetSymbolAddress((void**)&attn, g_attn);
    cudaGetSymbolAddress((void**)&res,  g_res);

    // 1) pack feat + write pos
    pack_kernel<<<4096, 256>>>(x, pos);
    // 2) squared norms
    sq_kernel<<<(CB * CS) / 8, 256>>>();
    // 3) Gram = feat * feat^T  (batched over CB)
    {
        dim3 g(CS / 64, CS / 64, CB);
        sgemm_kernel<true, false, false, false><<<g, 256>>>(
            feat, feat, nullptr, nullptr, gram,
            CS, CS, CD, (ll)CS * CD, (ll)CS * CD, (ll)CS * CS);
    }
    // 4) top-K neighbors
    topk_kernel<<<CB * CS, 256>>>();
    // 5) h = feat @ fc1_w + fc1_b
    {
        dim3 g(CT / 64, (CB * CS) / 64, 1);
        sgemm_kernel<false, false, false, true><<<g, 256>>>(
            feat, fc1_w, fc1_b, nullptr, h, CB * CS, CT, CD, 0, 0, 0);
        // q, k, v
        sgemm_kernel<false, false, false, false><<<g, 256>>>(
            h, wq_w, nullptr, nullptr, q, CB * CS, CT, CT, 0, 0, 0);
        sgemm_kernel<false, false, false, false><<<g, 256>>>(
            h, wk_w, nullptr, nullptr, k, CB * CS, CT, CT, 0, 0, 0);
        sgemm_kernel<false, false, false, false><<<g, 256>>>(
            h, wv_w, nullptr, nullptr, v, CB * CS, CT, CT, 0, 0, 0);
    }
    // 6) relation = q - gather(k)
    relation_kernel<<<CB * CS * CK, 256>>>();
    // 7) t1 = relu(rel @ g1_w + g1_b); attn = t1 @ g2_w + g2_b
    {
        dim3 g(CT / 64, (CB * CS * CK) / 64, 1);
        sgemm_kernel<false, true, false, true><<<g, 256>>>(
            rel, g1_w, g1_b, nullptr, t1, CB * CS * CK, CT, CT, 0, 0, 0);
        sgemm_kernel<false, false, false, true><<<g, 256>>>(
            t1, g2_w, g2_b, nullptr, attn, CB * CS * CK, CT, CT, 0, 0, 0);
    }
    // 8) softmax over K + weighted sum of gathered v
    softmax_res_kernel<<<CB * CS, 256>>>();
    // 9) out = res @ fc2_w + fc2_b + feat
    {
        dim3 g(CD / 64, (CB * CS) / 64, 1);
        sgemm_kernel<false, false, true, true><<<g, 256>>>(
            res, fc2_w, fc2_b, feat, outMain, CB * CS, CD, CT, 0, 0, 0);
    }
}

// round 2
// speedup vs baseline: 2.9036x; 2.9036x over previous
#include <cuda_runtime.h>
#include <cuda_bf16.h>

#define CB 4
#define CS 4096
#define CD 256
#define CT 256
#define CK 16
#define CIN 259

typedef long long ll;
typedef unsigned long long u64;
typedef __nv_bfloat16 bf16;

// ---------------- device scratch ----------------
__device__ bf16  g_A2[(size_t)CB * CS * 512];          // [hi(256) | lo(256)] per point, 16MB
__device__ float g_feat[CB * CS * CD];                 // fp32 features (residual + sq)
__device__ float g_sq[CB * CS];
__device__ float g_gram[(size_t)CB * CS * CS];         // 256MB
__device__ int   g_idx[CB * CS * CK];
__device__ bf16  g_h[CB * CS * CT];
__device__ float g_qg[CB * CS * CT];
__device__ float g_kg[CB * CS * CT];
__device__ float g_v[CB * CS * CT];
__device__ bf16  g_t1[(size_t)CB * CS * CK * CT];      // 128MB
__device__ bf16  g_attn[(size_t)CB * CS * CK * CT];    // 128MB
__device__ bf16  g_res[CB * CS * CT];
__device__ float g_Wqg[CT * CT];
__device__ float g_Wkg[CT * CT];
// transposed bf16 weights: 0=fc1,1=wv,2=g2,3=fc2,4=Wqg,5=Wkg
__device__ bf16  g_wT[6][CT * CT];

// ---------------- pack: x -> pos, feat fp32, A2 (hi|lo bf16) ----------------
__global__ void pack_kernel(const float* __restrict__ x, float* __restrict__ pos) {
    int i = blockIdx.x * blockDim.x + threadIdx.x;
    const int total = CB * CS * CIN;
    for (; i < total; i += gridDim.x * blockDim.x) {
        int bs = i / CIN;
        int c  = i % CIN;
        float v = x[i];
        if (c < 3) pos[bs * 3 + c] = v;
        else {
            int d = c - 3;
            g_feat[bs * CD + d] = v;
            bf16 hi = __float2bfloat16(v);
            float lo = v - __bfloat162float(hi);
            g_A2[(ll)bs * 512 + d]       = hi;
            g_A2[(ll)bs * 512 + 256 + d] = __float2bfloat16(lo);
        }
    }
}

// ---------------- sq ----------------
__global__ void sq_kernel() {
    int p = blockIdx.x * 8 + (threadIdx.x >> 5);
    int lane = threadIdx.x & 31;
    const float* f = g_feat + (ll)p * CD;
    float s = 0.f;
    #pragma unroll
    for (int d = lane; d < CD; d += 32) { float v = f[d]; s += v * v; }
    #pragma unroll
    for (int o = 16; o; o >>= 1) s += __shfl_xor_sync(0xFFFFFFFFu, s, o);
    if (!lane) g_sq[p] = s;
}

// ---------------- Wqg = wq@g1, Wkg = wk@g1 (fp32, tiny) ----------------
__global__ void wqk_prep_kernel(const float* __restrict__ wq, const float* __restrict__ wk,
                                const float* __restrict__ g1) {
    int r = blockIdx.x, c = threadIdx.x;
    float aq = 0.f, ak = 0.f;
    for (int k = 0; k < CT; k++) {
        float gv = g1[k * CT + c];
        aq += wq[r * CT + k] * gv;
        ak += wk[r * CT + k] * gv;
    }
    g_Wqg[r * CT + c] = aq;
    g_Wkg[r * CT + c] = ak;
}

// ---------------- transpose + convert weight: dst[n][k] = bf16(src[k][n]) ----------------
__global__ void tconv_kernel(const float* __restrict__ src, bf16* __restrict__ dst) {
    int n = blockIdx.x, k = threadIdx.x;
    dst[n * CT + k] = __float2bfloat16(src[k * CT + n]);
}

// ---------------- bf16 NT GEMM via mma.sync m16n8k16 ----------------
// C(MxN) = A(M x Kd, row stride lda) * B(N x Kd, row stride Kd)^T  [+bias] [+res] -> f32 or bf16
template <int OUT_BF16, bool BIAS, bool ADD_RES>
__global__ __launch_bounds__(256, 2)
void bmma_kernel(const bf16* __restrict__ A, const bf16* __restrict__ B,
                 const float* __restrict__ bias, const float* __restrict__ Rres,
                 float* __restrict__ Cf, bf16* __restrict__ Ch,
                 int M, int N, int Kd, int lda, ll sA, ll sB, ll sC) {
    const int tid = threadIdx.x;
    const int warp = tid >> 5, lane = tid & 31;
    const int wm = warp >> 2, wn = warp & 3;   // 2 x 4 warp grid
    const ll z = blockIdx.z;
    A += z * sA;
    B += z * sB;
    const int bm = blockIdx.y * 128, bn = blockIdx.x * 128;

    __shared__ bf16 As[128][40];
    __shared__ bf16 Bs[128][40];

    float acc[4][4][4];
    #pragma unroll
    for (int i = 0; i < 4; i++)
        #pragma unroll
        for (int j = 0; j < 4; j++)
            #pragma unroll
            for (int c = 0; c < 4; c++) acc[i][j][c] = 0.f;

    const int g  = lane >> 2;     // 0..7
    const int tc = lane & 3;      // 0..3

    const int lr  = tid >> 2;          // 0..63
    const int lc8 = (tid & 3) * 8;     // bf16 elems: 0,8,16,24
    const bf16* Ag  = A + (ll)(bm + lr) * lda + lc8;
    const bf16* Ag2 = A + (ll)(bm + lr + 64) * lda + lc8;
    const bf16* Bg  = B + (ll)(bn + lr) * Kd + lc8;
    const bf16* Bg2 = B + (ll)(bn + lr + 64) * Kd + lc8;

    for (int k0 = 0; k0 < Kd; k0 += 32) {
        *(uint4*)&As[lr][lc8]      = *(const uint4*)(Ag + k0);
        *(uint4*)&As[lr + 64][lc8] = *(const uint4*)(Ag2 + k0);
        *(uint4*)&Bs[lr][lc8]      = *(const uint4*)(Bg + k0);
        *(uint4*)&Bs[lr + 64][lc8] = *(const uint4*)(Bg2 + k0);
        __syncthreads();
        #pragma unroll
        for (int ks = 0; ks < 2; ks++) {
            const int kb = ks * 16;
            unsigned a_r[4][4], b_r[4][2];
            #pragma unroll
            for (int mt = 0; mt < 4; mt++) {
                int r0 = wm * 64 + mt * 16 + g;
                a_r[mt][0] = *(const unsigned*)&As[r0][kb + tc * 2];
                a_r[mt][1] = *(const unsigned*)&As[r0 + 8][kb + tc * 2];
                a_r[mt][2] = *(const unsigned*)&As[r0][kb + tc * 2 + 8];
                a_r[mt][3] = *(const unsigned*)&As[r0 + 8][kb + tc * 2 + 8];
            }
            #pragma unroll
            for (int nt = 0; nt < 4; nt++) {
                int c0 = wn * 32 + nt * 8 + g;
                b_r[nt][0] = *(const unsigned*)&Bs[c0][kb + tc * 2];
                b_r[nt][1] = *(const unsigned*)&Bs[c0][kb + tc * 2 + 8];
            }
            #pragma unroll
            for (int mt = 0; mt < 4; mt++)
                #pragma unroll
                for (int nt = 0; nt < 4; nt++)
                    asm volatile(
                        "mma.sync.aligned.m16n8k16.row.col.f32.bf16.bf16.f32 "
                        "{%0,%1,%2,%3}, {%4,%5,%6,%7}, {%8,%9}, {%0,%1,%2,%3};"
                        : "+f"(acc[mt][nt][0]), "+f"(acc[mt][nt][1]),
                          "+f"(acc[mt][nt][2]), "+f"(acc[mt][nt][3])
                        : "r"(a_r[mt][0]), "r"(a_r[mt][1]), "r"(a_r[mt][2]), "r"(a_r[mt][3]),
                          "r"(b_r[nt][0]), "r"(b_r[nt][1]));
        }
        __syncthreads();
    }

    // epilogue
    #pragma unroll
    for (int mt = 0; mt < 4; mt++) {
        int r0 = bm + wm * 64 + mt * 16 + g;
        #pragma unroll
        for (int nt = 0; nt < 4; nt++) {
            int c0 = bn + wn * 32 + nt * 8 + tc * 2;
            #pragma unroll
            for (int h = 0; h < 2; h++) {
                int rr = r0 + h * 8;
                float v0 = acc[mt][nt][h * 2 + 0];
                float v1 = acc[mt][nt][h * 2 + 1];
                if (BIAS) { v0 += bias[c0]; v1 += bias[c0 + 1]; }
                if (ADD_RES) {
                    v0 += Rres[(ll)rr * N + c0];
                    v1 += Rres[(ll)rr * N + c0 + 1];
                }
                if (OUT_BF16) {
                    __nv_bfloat162 pk;
                    pk.x = __float2bfloat16(v0);
                    pk.y = __float2bfloat16(v1);
                    *(__nv_bfloat162*)(Ch + z * sC + (ll)rr * N + c0) = pk;
                } else {
                    float2 pk = make_float2(v0, v1);
                    *(float2*)(Cf + z * sC + (ll)rr * N + c0) = pk;
                }
            }
        }
    }
}

// ---------------- top-K: bitonic sort + merge ----------------
__device__ __forceinline__ void ce_asc(u64& a, u64& b) { if (a > b) { u64 t = a; a = b; b = t; } }

__device__ __forceinline__ void bitonic_sort16(u64* k) {
    #pragma unroll
    for (int sz = 2; sz <= 16; sz <<= 1)
        #pragma unroll
        for (int j = sz >> 1; j > 0; j >>= 1)
            #pragma unroll
            for (int i = 0; i < 16; i++) {
                int l = i ^ j;
                if (l > i) {
                    if ((i & sz) == 0) ce_asc(k[i], k[l]);
                    else               ce_asc(k[l], k[i]);
                }
            }
}

__device__ __forceinline__ void bitonic_merge16(u64* k) {
    #pragma unroll
    for (int j = 8; j > 0; j >>= 1)
        #pragma unroll
        for (int i = 0; i < 16; i++)
            if ((i & j) == 0) ce_asc(k[i], k[i | j]);
}

__device__ __forceinline__ u64 umin64(u64 a, u64 b) { return a < b ? a : b; }

__global__ __launch_bounds__(256)
void topk_kernel() {
    const int row = blockIdx.x;                 // b*CS + n
    const int b = row >> 12;
    const float* __restrict__ G  = g_gram + ((size_t)b * CS + (row & (CS - 1))) * CS;
    const float* __restrict__ sq = g_sq + b * CS;
    const int t = threadIdx.x, lane = t & 31, warp = t >> 5;

    u64 keys[16];
    #pragma unroll
    for (int j = 0; j < 16; j++) {
        int m = t + j * 256;
        float sc = sq[m] - 2.0f * G[m];
        unsigned u = __float_as_uint(sc);
        u = (u & 0x80000000u) ? ~u : (u | 0x80000000u);
        keys[j] = ((u64)u << 32) | (unsigned)m;
    }
    bitonic_sort16(keys);

    // intra-warp merges: 256 -> 16 per warp (holder: lane 0)
    #pragma unroll
    for (int d = 1; d < 32; d <<= 1) {
        u64 p[16];
        #pragma unroll
        for (int i = 0; i < 16; i++) p[i] = __shfl_xor_sync(0xFFFFFFFFu, keys[i], d);
        if ((lane & (2 * d - 1)) == 0) {
            #pragma unroll
            for (int i = 0; i < 16; i++) keys[i] = umin64(keys[i], p[15 - i]);
            bitonic_merge16(keys);
        }
    }

    __shared__ u64 sk[8][16];
    if (lane == 0)
        #pragma unroll
        for (int i = 0; i < 16; i++) sk[warp][i] = keys[i];
    __syncthreads();

    if (warp == 0) {
        if (lane < 8)
            #pragma unroll
            for (int i = 0; i < 16; i++) keys[i] = sk[lane][i];
        #pragma unroll
        for (int d = 1; d < 8; d <<= 1) {
            u64 p[16];
            #pragma unroll
            for (int i = 0; i < 16; i++) p[i] = __shfl_xor_sync(0xFFFFFFFFu, keys[i], d);
            if (lane < 8 && (lane & (2 * d - 1)) == 0) {
                #pragma unroll
                for (int i = 0; i < 16; i++) keys[i] = umin64(keys[i], p[15 - i]);
                bitonic_merge16(keys);
            }
        }
        if (lane == 0)
            #pragma unroll
            for (int i = 0; i < 16; i++) g_idx[row * CK + i] = (int)(keys[i] & 0xFFFFFFFFu);
    }
}

// ---------------- t1[bnk,t] = relu(qg[bn,t] - kg[b,nb,t] + g1_b[t]) -> bf16 ----------------
__global__ __launch_bounds__(256)
void t1_kernel(const float* __restrict__ g1b) {
    const ll rk = blockIdx.x;          // bn*16 + k
    const int t = threadIdx.x;
    const ll bn = rk >> 4;
    const int b = (int)(bn >> 12);
    const int nb = g_idx[rk];
    float v = g_qg[bn * CT + t] - g_kg[((ll)b * CS + nb) * CT + t] + g1b[t];
    g_t1[rk * CT + t] = __float2bfloat16(v > 0.f ? v : 0.f);
}

// ---------------- softmax over K + weighted gather-sum of v -> res bf16 ----------------
__global__ __launch_bounds__(256)
void softmax_res_kernel() {
    const int bn = blockIdx.x;
    const int b = bn >> 12;
    const int t = threadIdx.x;
    __shared__ int nb[CK];
    if (t < CK) nb[t] = g_idx[bn * CK + t];
    __syncthreads();

    float lg[CK];
    float mx = -1e30f;
    #pragma unroll
    for (int k = 0; k < CK; k++) {
        lg[k] = __bfloat162float(g_attn[((ll)bn * CK + k) * CT + t]) * 0.0625f;
        mx = fmaxf(mx, lg[k]);
    }
    float se = 0.f;
    #pragma unroll
    for (int k = 0; k < CK; k++) { lg[k] = expf(lg[k] - mx); se += lg[k]; }
    const float inv = 1.f / se;
    float r = 0.f;
    #pragma unroll
    for (int k = 0; k < CK; k++)
        r += lg[k] * inv * g_v[((ll)b * CS + nb[k]) * CT + t];
    g_res[(ll)bn * CT + t] = __float2bfloat16(r);
}

// ---------------- launch ----------------
extern "C" void kernel_launch(void* const* d_in, const int* in_sizes, int n_in,
                              void* d_out, int out_size) {
    const float* x     = (const float*)d_in[0];
    const float* fc1_w = (const float*)d_in[1];
    const float* fc1_b = (const float*)d_in[2];
    const float* fc2_w = (const float*)d_in[3];
    const float* fc2_b = (const float*)d_in[4];
    const float* wq_w  = (const float*)d_in[5];
    const float* wk_w  = (const float*)d_in[6];
    const float* wv_w  = (const float*)d_in[7];
    const float* g1_w  = (const float*)d_in[8];
    const float* g1_b  = (const float*)d_in[9];
    const float* g2_w  = (const float*)d_in[10];
    const float* g2_b  = (const float*)d_in[11];

    float* out     = (float*)d_out;
    float* pos     = out;
    float* outMain = out + CB * CS * 3;

    bf16 *A2, *h, *t1, *attn, *res, *wT;
    float *feat, *gram, *qg, *kg, *v, *Wqg, *Wkg;
    cudaGetSymbolAddress((void**)&A2,   g_A2);
    cudaGetSymbolAddress((void**)&feat, g_feat);
    cudaGetSymbolAddress((void**)&gram, g_gram);
    cudaGetSymbolAddress((void**)&h,    g_h);
    cudaGetSymbolAddress((void**)&qg,   g_qg);
    cudaGetSymbolAddress((void**)&kg,   g_kg);
    cudaGetSymbolAddress((void**)&v,    g_v);
    cudaGetSymbolAddress((void**)&t1,   g_t1);
    cudaGetSymbolAddress((void**)&attn, g_attn);
    cudaGetSymbolAddress((void**)&res,  g_res);
    cudaGetSymbolAddress((void**)&Wqg,  g_Wqg);
    cudaGetSymbolAddress((void**)&Wkg,  g_Wkg);
    cudaGetSymbolAddress((void**)&wT,   g_wT);

    bf16* fc1T = wT + 0 * CT * CT;
    bf16* wvT  = wT + 1 * CT * CT;
    bf16* g2T  = wT + 2 * CT * CT;
    bf16* fc2T = wT + 3 * CT * CT;
    bf16* WqgT = wT + 4 * CT * CT;
    bf16* WkgT = wT + 5 * CT * CT;

    // 1) pack
    pack_kernel<<<4096, 256>>>(x, pos);
    sq_kernel<<<(CB * CS) / 8, 256>>>();

    // 2) weight prep
    wqk_prep_kernel<<<CT, CT>>>(wq_w, wk_w, g1_w);
    tconv_kernel<<<CT, CT>>>(fc1_w, fc1T);
    tconv_kernel<<<CT, CT>>>(wv_w, wvT);
    tconv_kernel<<<CT, CT>>>(g2_w, g2T);
    tconv_kernel<<<CT, CT>>>(fc2_w, fc2T);
    tconv_kernel<<<CT, CT>>>(Wqg, WqgT);
    tconv_kernel<<<CT, CT>>>(Wkg, WkgT);

    // 3) Gram = A2 @ A2^T  (K=512 exact bf16 split), batched over CB
    {
        dim3 g(CS / 128, CS / 128, CB);
        bmma_kernel<0, false, false><<<g, 256>>>(
            A2, A2, nullptr, nullptr, gram, nullptr,
            CS, CS, 512, 512, (ll)CS * 512, (ll)CS * 512, (ll)CS * CS);
    }
    // 4) topk
    topk_kernel<<<CB * CS, 256>>>();

    // 5) h = bf16(feat @ fc1 + b1)
    {
        dim3 g(CT / 128, (CB * CS) / 128, 1);
        bmma_kernel<1, true, false><<<g, 256>>>(
            A2, fc1T, fc1_b, nullptr, nullptr, h,
            CB * CS, CT, CD, 512, 0, 0, 0);
        // qg = h @ Wqg, kg = h @ Wkg, v = h @ wv  (fp32 out)
        bmma_kernel<0, false, false><<<g, 256>>>(
            h, WqgT, nullptr, nullptr, qg, nullptr, CB * CS, CT, CT, CT, 0, 0, 0);
        bmma_kernel<0, false, false><<<g, 256>>>(
            h, WkgT, nullptr, nullptr, kg, nullptr, CB * CS, CT, CT, CT, 0, 0, 0);
        bmma_kernel<0, false, false><<<g, 256>>>(
            h, wvT, nullptr, nullptr, v, nullptr, CB * CS, CT, CT, CT, 0, 0, 0);
    }

    // 6) t1 = relu(qg - gather(kg) + g1_b)  (bf16)
    t1_kernel<<<CB * CS * CK, 256>>>(g1_b);

    // 7) attn = bf16(t1 @ g2 + g2_b)
    {
        dim3 g(CT / 128, (CB * CS * CK) / 128, 1);
        bmma_kernel<1, true, false><<<g, 256>>>(
            t1, g2T, g2_b, nullptr, nullptr, attn,
            CB * CS * CK, CT, CT, CT, 0, 0, 0);
    }

    // 8) softmax + weighted v
    softmax_res_kernel<<<CB * CS, 256>>>();

    // 9) out = res @ fc2 + fc2_b + feat
    {
        dim3 g(CD / 128, (CB * CS) / 128, 1);
        bmma_kernel<0, true, true><<<g, 256>>>(
            res, fc2T, fc2_b, feat, outMain, nullptr,
            CB * CS, CD, CT, CT, 0, 0, 0);
    }
}

// round 4
// speedup vs baseline: 3.9083x; 1.3460x over previous
#include <cuda_runtime.h>
#include <cuda_bf16.h>
#include <cstdint>

#define CB 4
#define CS 4096
#define CD 256
#define CT 256
#define CK 16
#define CIN 259

typedef long long ll;
typedef unsigned long long u64;
typedef __nv_bfloat16 bf16;

// ---------------- device scratch ----------------
__device__ bf16  g_hi[(size_t)CB * CS * CD];           // bf16 features
__device__ float g_feat[CB * CS * CD];                 // fp32 features (residual)
__device__ float g_sq[CB * CS];
__device__ float g_gram[(size_t)CB * CS * CS];         // 256MB
__device__ int   g_idx[CB * CS * CK];
__device__ bf16  g_h[CB * CS * CT];
__device__ float g_qg[CB * CS * CT];
__device__ float g_kg[CB * CS * CT];
__device__ float g_v[CB * CS * CT];
__device__ bf16  g_t1[(size_t)CB * CS * CK * CT];      // 128MB
__device__ bf16  g_attn[(size_t)CB * CS * CK * CT];    // 128MB
__device__ bf16  g_res[CB * CS * CT];
// transposed bf16 weights: 0=fc1,1=wv,2=g2,3=fc2,4=Wqg,5=Wkg
__device__ bf16  g_wT[6][CT * CT];

// ---------------- cp.async helpers ----------------
__device__ __forceinline__ uint32_t smem_u32(const void* p) {
    return (uint32_t)__cvta_generic_to_shared(p);
}
__device__ __forceinline__ void cp_async16(uint32_t s, const void* g) {
    asm volatile("cp.async.cg.shared.global [%0], [%1], 16;" :: "r"(s), "l"(g));
}
__device__ __forceinline__ void cp_commit() {
    asm volatile("cp.async.commit_group;" ::: "memory");
}
__device__ __forceinline__ void cp_wait1() {
    asm volatile("cp.async.wait_group 1;" ::: "memory");
}

// ---------------- pipelined bf16 HMMA GEMM ----------------
// C(MxN) = A(M x Kd, row stride lda) * B(N x Kd, stride Kd)^T [+bias][+res]
// Tile 128x128, K-stage 32, 3-stage cp.async pipeline, 8 warps (2x4).
static constexpr int ST_ROWB = 80;                 // bytes per smem row (32 bf16 + pad)
static constexpr int ST_HALF = 128 * ST_ROWB;      // 10240 bytes (A or B)
static constexpr int ST_BYTES = 2 * ST_HALF;       // per stage
static constexpr int SOFF_STG = 1024;              // bias in [0,512)
static constexpr int SMEM_MMA = SOFF_STG + 3 * ST_BYTES;  // 62464

template <int OUT_BF16, bool BIAS, bool ADD_RES>
__global__ __launch_bounds__(256, 2)
void mma_gemm(const bf16* __restrict__ A, const bf16* __restrict__ B,
              const float* __restrict__ bias, const float* __restrict__ Rres,
              float* __restrict__ Cf, bf16* __restrict__ Ch,
              int N, int Kd, int lda, ll sA, ll sB, ll sC) {
    extern __shared__ char smem[];
    const int tid = threadIdx.x;
    const int warp = tid >> 5, lane = tid & 31;
    const int wm = warp >> 2, wn = warp & 3;
    const int g = lane >> 2, tc = lane & 3;
    const uint32_t sbase = smem_u32(smem);
    const ll z = blockIdx.z;
    const int bm = blockIdx.y * 128, bn = blockIdx.x * 128;
    const bf16* Ag = A + z * sA + (ll)bm * lda;
    const bf16* Bg = B + z * sB + (ll)bn * Kd;

    float* sbias = (float*)smem;
    if (BIAS && tid < 128) sbias[tid] = bias[bn + tid];

    float acc[4][4][4];
    #pragma unroll
    for (int i = 0; i < 4; i++)
        #pragma unroll
        for (int j = 0; j < 4; j++)
            #pragma unroll
            for (int c = 0; c < 4; c++) acc[i][j][c] = 0.f;

    const int nch = Kd >> 5;
    const int lr = tid >> 2;          // 0..63 -> used twice (A rows 0..127 via 2 chunks)
    const int lc = (tid & 3) << 3;    // bf16 col: 0,8,16,24

    // stage loader: K-chunk i into slot s
    auto load_stage = [&](int i, int s) {
        if (i < nch) {
            const int k0 = i << 5;
            uint32_t sa = sbase + SOFF_STG + s * ST_BYTES;
            uint32_t sb = sa + ST_HALF;
            #pragma unroll
            for (int j = 0; j < 2; j++) {
                int r = lr + j * 64;
                cp_async16(sa + r * ST_ROWB + lc * 2, Ag + (ll)r * lda + k0 + lc);
                cp_async16(sb + r * ST_ROWB + lc * 2, Bg + (ll)r * Kd + k0 + lc);
            }
        }
        cp_commit();
    };

    load_stage(0, 0);
    load_stage(1, 1);

    for (int i = 0; i < nch; i++) {
        cp_wait1();
        __syncthreads();
        load_stage(i + 2, (i + 2) % 3);

        const char* sa = smem + SOFF_STG + (i % 3) * ST_BYTES;
        const char* sb = sa + ST_HALF;
        #pragma unroll
        for (int ks = 0; ks < 2; ks++) {
            const int kb = ks * 16;
            unsigned a_r[4][4], b_r[4][2];
            #pragma unroll
            for (int mt = 0; mt < 4; mt++) {
                int r0 = wm * 64 + mt * 16 + g;
                const char* p0 = sa + r0 * ST_ROWB + (kb + tc * 2) * 2;
                a_r[mt][0] = *(const unsigned*)(p0);
                a_r[mt][1] = *(const unsigned*)(p0 + 8 * ST_ROWB);
                a_r[mt][2] = *(const unsigned*)(p0 + 16);
                a_r[mt][3] = *(const unsigned*)(p0 + 8 * ST_ROWB + 16);
            }
            #pragma unroll
            for (int nt = 0; nt < 4; nt++) {
                int c0 = wn * 32 + nt * 8 + g;
                const char* p0 = sb + c0 * ST_ROWB + (kb + tc * 2) * 2;
                b_r[nt][0] = *(const unsigned*)(p0);
                b_r[nt][1] = *(const unsigned*)(p0 + 16);
            }
            #pragma unroll
            for (int mt = 0; mt < 4; mt++)
                #pragma unroll
                for (int nt = 0; nt < 4; nt++)
                    asm volatile(
                        "mma.sync.aligned.m16n8k16.row.col.f32.bf16.bf16.f32 "
                        "{%0,%1,%2,%3}, {%4,%5,%6,%7}, {%8,%9}, {%0,%1,%2,%3};"
                        : "+f"(acc[mt][nt][0]), "+f"(acc[mt][nt][1]),
                          "+f"(acc[mt][nt][2]), "+f"(acc[mt][nt][3])
                        : "r"(a_r[mt][0]), "r"(a_r[mt][1]), "r"(a_r[mt][2]), "r"(a_r[mt][3]),
                          "r"(b_r[nt][0]), "r"(b_r[nt][1]));
        }
    }

    // epilogue
    #pragma unroll
    for (int mt = 0; mt < 4; mt++) {
        int r0 = bm + wm * 64 + mt * 16 + g;
        #pragma unroll
        for (int nt = 0; nt < 4; nt++) {
            int lcol = wn * 32 + nt * 8 + tc * 2;
            int c0 = bn + lcol;
            #pragma unroll
            for (int h = 0; h < 2; h++) {
                int rr = r0 + h * 8;
                float v0 = acc[mt][nt][h * 2 + 0];
                float v1 = acc[mt][nt][h * 2 + 1];
                if (BIAS) { v0 += sbias[lcol]; v1 += sbias[lcol + 1]; }
                if (ADD_RES) {
                    v0 += Rres[(ll)rr * N + c0];
                    v1 += Rres[(ll)rr * N + c0 + 1];
                }
                if (OUT_BF16) {
                    __nv_bfloat162 pk;
                    pk.x = __float2bfloat16(v0);
                    pk.y = __float2bfloat16(v1);
                    *(__nv_bfloat162*)(Ch + z * sC + (ll)rr * N + c0) = pk;
                } else {
                    *(float2*)(Cf + z * sC + (ll)rr * N + c0) = make_float2(v0, v1);
                }
            }
        }
    }
}

// ---------------- pack + sq fused: one block per point ----------------
__global__ __launch_bounds__(256)
void packsq_kernel(const float* __restrict__ x, float* __restrict__ pos) {
    const int p = blockIdx.x;
    const int t = threadIdx.x;
    const float* xr = x + (ll)p * CIN;
    float v = xr[3 + t];
    g_feat[(ll)p * CD + t] = v;
    g_hi[(ll)p * CD + t] = __float2bfloat16(v);
    if (t < 3) pos[p * 3 + t] = xr[t];
    // block reduce v*v
    float s = v * v;
    #pragma unroll
    for (int o = 16; o; o >>= 1) s += __shfl_xor_sync(0xFFFFFFFFu, s, o);
    __shared__ float ws[8];
    if ((t & 31) == 0) ws[t >> 5] = s;
    __syncthreads();
    if (t == 0) {
        float tot = 0.f;
        #pragma unroll
        for (int w = 0; w < 8; w++) tot += ws[w];
        g_sq[p] = tot;
    }
}

// Wqg = wq@g1, Wkg = wk@g1, written transposed as bf16
__global__ void wqk_prep_kernel(const float* __restrict__ wq, const float* __restrict__ wk,
                                const float* __restrict__ g1) {
    int r = blockIdx.x, c = threadIdx.x;
    float aq = 0.f, ak = 0.f;
    for (int k = 0; k < CT; k++) {
        float gv = g1[k * CT + c];
        aq += wq[r * CT + k] * gv;
        ak += wk[r * CT + k] * gv;
    }
    g_wT[4][c * CT + r] = __float2bfloat16(aq);
    g_wT[5][c * CT + r] = __float2bfloat16(ak);
}

__global__ void tconv4_kernel(const float* __restrict__ fc1, const float* __restrict__ wv,
                              const float* __restrict__ g2, const float* __restrict__ fc2) {
    int n = blockIdx.x, k = threadIdx.x, w = blockIdx.y;
    const float* src = (w == 0) ? fc1 : (w == 1) ? wv : (w == 2) ? g2 : fc2;
    g_wT[w][n * CT + k] = __float2bfloat16(src[k * CT + n]);
}

// ---------------- top-K (bitonic) ----------------
__device__ __forceinline__ void ce_asc(u64& a, u64& b) { if (a > b) { u64 t = a; a = b; b = t; } }
__device__ __forceinline__ void bitonic_sort16(u64* k) {
    #pragma unroll
    for (int sz = 2; sz <= 16; sz <<= 1)
        #pragma unroll
        for (int j = sz >> 1; j > 0; j >>= 1)
            #pragma unroll
            for (int i = 0; i < 16; i++) {
                int l = i ^ j;
                if (l > i) {
                    if ((i & sz) == 0) ce_asc(k[i], k[l]);
                    else               ce_asc(k[l], k[i]);
                }
            }
}
__device__ __forceinline__ void bitonic_merge16(u64* k) {
    #pragma unroll
    for (int j = 8; j > 0; j >>= 1)
        #pragma unroll
        for (int i = 0; i < 16; i++)
            if ((i & j) == 0) ce_asc(k[i], k[i | j]);
}
__device__ __forceinline__ u64 umin64(u64 a, u64 b) { return a < b ? a : b; }

__global__ __launch_bounds__(256)
void topk_kernel() {
    const int row = blockIdx.x;
    const int b = row >> 12;
    const float* __restrict__ G  = g_gram + ((size_t)b * CS + (row & (CS - 1))) * CS;
    const float* __restrict__ sq = g_sq + b * CS;
    const int t = threadIdx.x, lane = t & 31, warp = t >> 5;

    u64 keys[16];
    #pragma unroll
    for (int j = 0; j < 16; j++) {
        int m = t + j * 256;
        float sc = sq[m] - 2.0f * G[m];
        unsigned u = __float_as_uint(sc);
        u = (u & 0x80000000u) ? ~u : (u | 0x80000000u);
        keys[j] = ((u64)u << 32) | (unsigned)m;
    }
    bitonic_sort16(keys);
    #pragma unroll
    for (int d = 1; d < 32; d <<= 1) {
        u64 p[16];
        #pragma unroll
        for (int i = 0; i < 16; i++) p[i] = __shfl_xor_sync(0xFFFFFFFFu, keys[i], d);
        if ((lane & (2 * d - 1)) == 0) {
            #pragma unroll
            for (int i = 0; i < 16; i++) keys[i] = umin64(keys[i], p[15 - i]);
            bitonic_merge16(keys);
        }
    }
    __shared__ u64 sk[8][16];
    if (lane == 0)
        #pragma unroll
        for (int i = 0; i < 16; i++) sk[warp][i] = keys[i];
    __syncthreads();
    if (warp == 0) {
        if (lane < 8)
            #pragma unroll
            for (int i = 0; i < 16; i++) keys[i] = sk[lane][i];
        #pragma unroll
        for (int d = 1; d < 8; d <<= 1) {
            u64 p[16];
            #pragma unroll
            for (int i = 0; i < 16; i++) p[i] = __shfl_xor_sync(0xFFFFFFFFu, keys[i], d);
            if (lane < 8 && (lane & (2 * d - 1)) == 0) {
                #pragma unroll
                for (int i = 0; i < 16; i++) keys[i] = umin64(keys[i], p[15 - i]);
                bitonic_merge16(keys);
            }
        }
        if (lane == 0)
            #pragma unroll
            for (int i = 0; i < 16; i++) g_idx[row * CK + i] = (int)(keys[i] & 0xFFFFFFFFu);
    }
}

// ---------------- t1 = relu(qg + g1_b - gather(kg)) -> bf16, one block per point ----------------
__global__ __launch_bounds__(256)
void t1_kernel(const float* __restrict__ g1b) {
    const int bn = blockIdx.x;
    const int b = bn >> 12;
    const int t = threadIdx.x;
    __shared__ float qrow[CT];
    __shared__ int nb[CK];
    qrow[t] = g_qg[(ll)bn * CT + t] + g1b[t];
    if (t < CK) nb[t] = g_idx[bn * CK + t];
    __syncthreads();
    #pragma unroll
    for (int k = 0; k < CK; k++) {
        float v = qrow[t] - g_kg[((ll)b * CS + nb[k]) * CT + t];
        g_t1[((ll)bn * CK + k) * CT + t] = __float2bfloat16(v > 0.f ? v : 0.f);
    }
}

// ---------------- softmax over K + weighted gather-sum ----------------
__global__ __launch_bounds__(256)
void softmax_res_kernel() {
    const int bn = blockIdx.x;
    const int b = bn >> 12;
    const int t = threadIdx.x;
    __shared__ int nb[CK];
    if (t < CK) nb[t] = g_idx[bn * CK + t];
    __syncthreads();
    float lg[CK];
    float mx = -1e30f;
    #pragma unroll
    for (int k = 0; k < CK; k++) {
        lg[k] = __bfloat162float(g_attn[((ll)bn * CK + k) * CT + t]) * 0.0625f;
        mx = fmaxf(mx, lg[k]);
    }
    float se = 0.f;
    #pragma unroll
    for (int k = 0; k < CK; k++) { lg[k] = expf(lg[k] - mx); se += lg[k]; }
    const float inv = 1.f / se;
    float r = 0.f;
    #pragma unroll
    for (int k = 0; k < CK; k++)
        r += lg[k] * inv * g_v[((ll)b * CS + nb[k]) * CT + t];
    g_res[(ll)bn * CT + t] = __float2bfloat16(r);
}

// ---------------- launch ----------------
extern "C" void kernel_launch(void* const* d_in, const int* in_sizes, int n_in,
                              void* d_out, int out_size) {
    const float* x     = (const float*)d_in[0];
    const float* fc1_w = (const float*)d_in[1];
    const float* fc1_b = (const float*)d_in[2];
    const float* fc2_w = (const float*)d_in[3];
    const float* fc2_b = (const float*)d_in[4];
    const float* wq_w  = (const float*)d_in[5];
    const float* wk_w  = (const float*)d_in[6];
    const float* wv_w  = (const float*)d_in[7];
    const float* g1_w  = (const float*)d_in[8];
    const float* g1_b  = (const float*)d_in[9];
    const float* g2_w  = (const float*)d_in[10];
    const float* g2_b  = (const float*)d_in[11];

    float* out     = (float*)d_out;
    float* pos     = out;
    float* outMain = out + CB * CS * 3;

    bf16 *hi, *h, *t1, *attn, *res, *wT;
    float *feat, *gram, *qg, *kg, *v;
    cudaGetSymbolAddress((void**)&hi,   g_hi);
    cudaGetSymbolAddress((void**)&feat, g_feat);
    cudaGetSymbolAddress((void**)&gram, g_gram);
    cudaGetSymbolAddress((void**)&h,    g_h);
    cudaGetSymbolAddress((void**)&qg,   g_qg);
    cudaGetSymbolAddress((void**)&kg,   g_kg);
    cudaGetSymbolAddress((void**)&v,    g_v);
    cudaGetSymbolAddress((void**)&t1,   g_t1);
    cudaGetSymbolAddress((void**)&attn, g_attn);
    cudaGetSymbolAddress((void**)&res,  g_res);
    cudaGetSymbolAddress((void**)&wT,   g_wT);

    bf16* fc1T = wT + 0 * CT * CT;
    bf16* wvT  = wT + 1 * CT * CT;
    bf16* g2T  = wT + 2 * CT * CT;
    bf16* fc2T = wT + 3 * CT * CT;
    bf16* WqgT = wT + 4 * CT * CT;
    bf16* WkgT = wT + 5 * CT * CT;

    cudaFuncSetAttribute(mma_gemm<0, false, false>, cudaFuncAttributeMaxDynamicSharedMemorySize, SMEM_MMA);
    cudaFuncSetAttribute(mma_gemm<1, true, false>,  cudaFuncAttributeMaxDynamicSharedMemorySize, SMEM_MMA);
    cudaFuncSetAttribute(mma_gemm<0, true, true>,   cudaFuncAttributeMaxDynamicSharedMemorySize, SMEM_MMA);

    // 1) pack + norms + weight prep
    packsq_kernel<<<CB * CS, 256>>>(x, pos);
    wqk_prep_kernel<<<CT, CT>>>(wq_w, wk_w, g1_w);
    {
        dim3 g(CT, 4, 1);
        tconv4_kernel<<<g, CT>>>(fc1_w, wv_w, g2_w, fc2_w);
    }

    // 2) Gram = hi @ hi^T (bf16, K=256), batched over CB
    {
        dim3 g(CS / 128, CS / 128, CB);
        mma_gemm<0, false, false><<<g, 256, SMEM_MMA>>>(
            hi, hi, nullptr, nullptr, gram, nullptr,
            CS, CD, CD, (ll)CS * CD, (ll)CS * CD, (ll)CS * CS);
    }
    // 3) topk
    topk_kernel<<<CB * CS, 256>>>();

    // 4) h = bf16(feat @ fc1 + b1); qg/kg/v projections
    {
        dim3 g(CT / 128, (CB * CS) / 128, 1);
        mma_gemm<1, true, false><<<g, 256, SMEM_MMA>>>(
            hi, fc1T, fc1_b, nullptr, nullptr, h, CT, CD, CD, 0, 0, 0);
        mma_gemm<0, false, false><<<g, 256, SMEM_MMA>>>(
            h, WqgT, nullptr, nullptr, qg, nullptr, CT, CT, CT, 0, 0, 0);
        mma_gemm<0, false, false><<<g, 256, SMEM_MMA>>>(
            h, WkgT, nullptr, nullptr, kg, nullptr, CT, CT, CT, 0, 0, 0);
        mma_gemm<0, false, false><<<g, 256, SMEM_MMA>>>(
            h, wvT, nullptr, nullptr, v, nullptr, CT, CT, CT, 0, 0, 0);
    }

    // 5) t1 = relu(qg + g1_b - gather(kg))
    t1_kernel<<<CB * CS, 256>>>(g1_b);

    // 6) attn = bf16(t1 @ g2 + g2_b)
    {
        dim3 g(CT / 128, (CB * CS * CK) / 128, 1);
        mma_gemm<1, true, false><<<g, 256, SMEM_MMA>>>(
            t1, g2T, g2_b, nullptr, nullptr, attn, CT, CT, CT, 0, 0, 0);
    }

    // 7) softmax + weighted v
    softmax_res_kernel<<<CB * CS, 256>>>();

    // 8) out = res @ fc2 + fc2_b + feat
    {
        dim3 g(CD / 128, (CB * CS) / 128, 1);
        mma_gemm<0, true, true><<<g, 256, SMEM_MMA>>>(
            res, fc2T, fc2_b, feat, outMain, nullptr, CD, CT, CT, 0, 0, 0);
    }
}